// round 4
// baseline (speedup 1.0000x reference)
#include <cuda_runtime.h>
#include <math.h>

#define N_NODES 50000
#define F_IN 128
#define HID 256
#define NCLS 40
#define N_EDGES 600000
#define BN_EPS 1e-5f

// Scratch (static device globals -- no runtime allocation allowed)
__device__ float g_h0[N_NODES * F_IN];    // BN0(x)
__device__ float g_agg1[N_NODES * F_IN];  // h0 + scatter
__device__ float g_h1[N_NODES * HID];     // relu(BN1(agg1 @ W1 + b1))
__device__ float g_agg2[N_NODES * HID];   // h1 + scatter

__device__ __forceinline__ int clamp_idx(int i) {
    i = i < 0 ? 0 : i;
    return i >= N_NODES ? N_NODES - 1 : i;
}

// ---------------------------------------------------------------------------
// K1: BN0 over input features; writes g_h0 and initializes g_agg1 (self term)
// ---------------------------------------------------------------------------
__global__ void bn0_kernel(const float4* __restrict__ x,
                           const float* __restrict__ g, const float* __restrict__ b,
                           const float* __restrict__ m, const float* __restrict__ v) {
    int idx = blockIdx.x * blockDim.x + threadIdx.x;
    const int total = N_NODES * (F_IN / 4);
    if (idx >= total) return;
    int c = (idx & (F_IN / 4 - 1)) * 4;
    float4 xv = x[idx];
    float4 o;
    o.x = (xv.x - __ldg(m + c + 0)) * (__ldg(g + c + 0) * rsqrtf(__ldg(v + c + 0) + BN_EPS)) + __ldg(b + c + 0);
    o.y = (xv.y - __ldg(m + c + 1)) * (__ldg(g + c + 1) * rsqrtf(__ldg(v + c + 1) + BN_EPS)) + __ldg(b + c + 1);
    o.z = (xv.z - __ldg(m + c + 2)) * (__ldg(g + c + 2) * rsqrtf(__ldg(v + c + 2) + BN_EPS)) + __ldg(b + c + 2);
    o.w = (xv.w - __ldg(m + c + 3)) * (__ldg(g + c + 3) * rsqrtf(__ldg(v + c + 3) + BN_EPS)) + __ldg(b + c + 3);
    ((float4*)g_h0)[idx] = o;
    ((float4*)g_agg1)[idx] = o;
}

// ---------------------------------------------------------------------------
// K2: edge scatter-add, F=128. One warp per edge; lane handles 4 floats.
// ---------------------------------------------------------------------------
__global__ void scatter128_kernel(const int* __restrict__ src,
                                  const int* __restrict__ dst) {
    int t = blockIdx.x * blockDim.x + threadIdx.x;
    int e = t >> 5;
    if (e >= N_EDGES) return;
    int lane = t & 31;
    int s = clamp_idx(__ldg(src + e));
    int d = clamp_idx(__ldg(dst + e));
    float4 hv = ((const float4*)(g_h0 + (size_t)s * F_IN))[lane];
    float* dp = g_agg1 + (size_t)d * F_IN + lane * 4;
    atomicAdd(dp + 0, hv.x);
    atomicAdd(dp + 1, hv.y);
    atomicAdd(dp + 2, hv.z);
    atomicAdd(dp + 3, hv.w);
}

// ---------------------------------------------------------------------------
// K3: GEMM1 [50000,128]x[128,256] + bias + BN1 + ReLU.
//     Writes g_h1 and initializes g_agg2 (self term).
//     64x64 tile, BK=64 (2 k-stages), 256 threads, 4x4 per thread.
// ---------------------------------------------------------------------------
__global__ void gemm1_kernel(const float* __restrict__ W1, const float* __restrict__ b1,
                             const float* __restrict__ bg, const float* __restrict__ bb,
                             const float* __restrict__ bm, const float* __restrict__ bv) {
    __shared__ __align__(16) float sA[64][68];
    __shared__ __align__(16) float sB[64][68];
    const float* A = g_agg1;
    int tid = threadIdx.x;
    int block_m = blockIdx.x * 64;
    int block_n = blockIdx.y * 64;
    int tx = tid & 15, ty = tid >> 4;

    float acc[4][4];
#pragma unroll
    for (int i = 0; i < 4; i++)
#pragma unroll
        for (int j = 0; j < 4; j++) acc[i][j] = 0.f;

    for (int kk = 0; kk < F_IN; kk += 64) {
        // Load A tile: 64 rows x 64 cols = 1024 float4, 4 per thread
#pragma unroll
        for (int i = 0; i < 4; i++) {
            int f4 = tid + i * 256;           // 0..1023
            int row = f4 >> 4;                // 0..63
            int c4 = f4 & 15;                 // 0..15
            int gr = block_m + row;
            float4 val = make_float4(0.f, 0.f, 0.f, 0.f);
            if (gr < N_NODES)
                val = ((const float4*)(A + (size_t)gr * F_IN + kk))[c4];
            *(float4*)&sA[row][c4 * 4] = val;
        }
        // Load B tile: W1 is [128][256] row-major; rows kk..kk+63, cols block_n..+63
#pragma unroll
        for (int i = 0; i < 4; i++) {
            int f4 = tid + i * 256;
            int k = f4 >> 4;
            int c4 = f4 & 15;
            float4 val = ((const float4*)(W1 + (size_t)(kk + k) * HID + block_n))[c4];
            *(float4*)&sB[k][c4 * 4] = val;
        }
        __syncthreads();

#pragma unroll
        for (int k = 0; k < 64; k++) {
            float a[4], bvreg[4];
#pragma unroll
            for (int i = 0; i < 4; i++) a[i] = sA[ty * 4 + i][k];
#pragma unroll
            for (int j = 0; j < 4; j++) bvreg[j] = sB[k][tx * 4 + j];
#pragma unroll
            for (int i = 0; i < 4; i++)
#pragma unroll
                for (int j = 0; j < 4; j++) acc[i][j] += a[i] * bvreg[j];
        }
        __syncthreads();
    }

    // Epilogue: + bias, BN1 (eval), ReLU -> g_h1 and g_agg2
#pragma unroll
    for (int j = 0; j < 4; j++) {
        int c = block_n + tx * 4 + j;
        float s = __ldg(bg + c) * rsqrtf(__ldg(bv + c) + BN_EPS);
        float mu = __ldg(bm + c);
        float be = __ldg(bb + c);
        float bias = __ldg(b1 + c);
#pragma unroll
        for (int i = 0; i < 4; i++) {
            int gr = block_m + ty * 4 + i;
            if (gr < N_NODES) {
                float val = acc[i][j] + bias;
                val = (val - mu) * s + be;
                val = fmaxf(val, 0.f);
                size_t off = (size_t)gr * HID + c;
                g_h1[off] = val;
                g_agg2[off] = val;
            }
        }
    }
}

// ---------------------------------------------------------------------------
// K4: edge scatter-add, F=256. One warp per edge; lane handles 8 floats.
// ---------------------------------------------------------------------------
__global__ void scatter256_kernel(const int* __restrict__ src,
                                  const int* __restrict__ dst) {
    int t = blockIdx.x * blockDim.x + threadIdx.x;
    int e = t >> 5;
    if (e >= N_EDGES) return;
    int lane = t & 31;
    int s = clamp_idx(__ldg(src + e));
    int d = clamp_idx(__ldg(dst + e));
    const float4* sp = (const float4*)(g_h1 + (size_t)s * HID);
    float4 h0v = sp[lane];
    float4 h1v = sp[lane + 32];
    float* dp = g_agg2 + (size_t)d * HID;
    atomicAdd(dp + lane * 4 + 0, h0v.x);
    atomicAdd(dp + lane * 4 + 1, h0v.y);
    atomicAdd(dp + lane * 4 + 2, h0v.z);
    atomicAdd(dp + lane * 4 + 3, h0v.w);
    atomicAdd(dp + 128 + lane * 4 + 0, h1v.x);
    atomicAdd(dp + 128 + lane * 4 + 1, h1v.y);
    atomicAdd(dp + 128 + lane * 4 + 2, h1v.z);
    atomicAdd(dp + 128 + lane * 4 + 3, h1v.w);
}

// ---------------------------------------------------------------------------
// K5: GEMM2 [50000,256]x[256,40] + bias -> out. One thread per row,
//     W2 staged in smem (40KB), broadcast reads.
// ---------------------------------------------------------------------------
__global__ void gemm2_kernel(const float* __restrict__ W2, const float* __restrict__ b2,
                             float* __restrict__ out) {
    __shared__ float sW[HID * NCLS];  // 40KB
    int tid = threadIdx.x;
    for (int i = tid; i < HID * NCLS; i += blockDim.x) sW[i] = W2[i];
    __syncthreads();

    int row = blockIdx.x * blockDim.x + tid;
    if (row >= N_NODES) return;

    float acc[NCLS];
#pragma unroll
    for (int c = 0; c < NCLS; c++) acc[c] = 0.f;

    const float4* ap = (const float4*)(g_agg2 + (size_t)row * HID);
#pragma unroll 4
    for (int k4 = 0; k4 < HID / 4; k4++) {
        float4 a = ap[k4];
        const float* w0 = &sW[(k4 * 4 + 0) * NCLS];
        const float* w1 = &sW[(k4 * 4 + 1) * NCLS];
        const float* w2 = &sW[(k4 * 4 + 2) * NCLS];
        const float* w3 = &sW[(k4 * 4 + 3) * NCLS];
#pragma unroll
        for (int c = 0; c < NCLS; c++) {
            acc[c] += a.x * w0[c];
            acc[c] += a.y * w1[c];
            acc[c] += a.z * w2[c];
            acc[c] += a.w * w3[c];
        }
    }

    float* op = out + (size_t)row * NCLS;
#pragma unroll
    for (int c = 0; c < NCLS; c++) op[c] = acc[c] + __ldg(b2 + c);
}

// ---------------------------------------------------------------------------
extern "C" void kernel_launch(void* const* d_in, const int* in_sizes, int n_in,
                              void* d_out, int out_size) {
    const float* x = (const float*)d_in[0];
    const int* ei = (const int*)d_in[1];   // int32: jax x64-disabled downcasts int64
    const float* bn0g = (const float*)d_in[2];
    const float* bn0b = (const float*)d_in[3];
    const float* bn0m = (const float*)d_in[4];
    const float* bn0v = (const float*)d_in[5];
    const float* W1 = (const float*)d_in[6];
    const float* b1 = (const float*)d_in[7];
    const float* bn1g = (const float*)d_in[8];
    const float* bn1b = (const float*)d_in[9];
    const float* bn1m = (const float*)d_in[10];
    const float* bn1v = (const float*)d_in[11];
    const float* W2 = (const float*)d_in[12];
    const float* b2 = (const float*)d_in[13];
    float* out = (float*)d_out;

    const int* src = ei;
    const int* dst = ei + N_EDGES;

    // K1: BN0 -> g_h0, g_agg1
    {
        int total = N_NODES * (F_IN / 4);
        int blocks = (total + 255) / 256;
        bn0_kernel<<<blocks, 256>>>((const float4*)x, bn0g, bn0b, bn0m, bn0v);
    }
    // K2: scatter-add into g_agg1
    {
        long long threads = (long long)N_EDGES * 32;
        int blocks = (int)((threads + 255) / 256);
        scatter128_kernel<<<blocks, 256>>>(src, dst);
    }
    // K3: GEMM1 + BN1 + ReLU -> g_h1, g_agg2
    {
        dim3 grid((N_NODES + 63) / 64, HID / 64);
        gemm1_kernel<<<grid, 256>>>(W1, b1, bn1g, bn1b, bn1m, bn1v);
    }
    // K4: scatter-add into g_agg2
    {
        long long threads = (long long)N_EDGES * 32;
        int blocks = (int)((threads + 255) / 256);
        scatter256_kernel<<<blocks, 256>>>(src, dst);
    }
    // K5: GEMM2 -> out
    {
        int blocks = (N_NODES + 255) / 256;
        gemm2_kernel<<<blocks, 256>>>(W2, b2, out);
    }
}

// round 6
// speedup vs baseline: 2.4657x; 2.4657x over previous
#include <cuda_runtime.h>
#include <math.h>

#define N_NODES 50000
#define F_IN 128
#define HID 256
#define NCLS 40
#define N_EDGES 600000
#define BN_EPS 1e-5f

// Scratch (static device globals -- no runtime allocation allowed)
__device__ float g_h0[N_NODES * F_IN];    // BN0(x)
__device__ float g_agg1[N_NODES * F_IN];  // h0 + scatter
__device__ float g_h1[N_NODES * HID];     // relu(BN1(agg1 @ W1 + b1))
__device__ float g_z[N_NODES * NCLS];     // h1 @ W2 (pre-aggregation logits)

__device__ __forceinline__ int clamp_idx(int i) {
    i = i < 0 ? 0 : i;
    return i >= N_NODES ? N_NODES - 1 : i;
}

__device__ __forceinline__ void red_add_v4(float* p, float4 v) {
    asm volatile("red.global.add.v4.f32 [%0], {%1, %2, %3, %4};"
                 :: "l"(p), "f"(v.x), "f"(v.y), "f"(v.z), "f"(v.w)
                 : "memory");
}

// ---------------------------------------------------------------------------
// K1: BN0 over input features; writes g_h0 and initializes g_agg1 (self term)
// ---------------------------------------------------------------------------
__global__ void bn0_kernel(const float4* __restrict__ x,
                           const float* __restrict__ g, const float* __restrict__ b,
                           const float* __restrict__ m, const float* __restrict__ v) {
    int idx = blockIdx.x * blockDim.x + threadIdx.x;
    const int total = N_NODES * (F_IN / 4);
    if (idx >= total) return;
    int c = (idx & (F_IN / 4 - 1)) * 4;
    float4 xv = x[idx];
    float4 o;
    o.x = (xv.x - __ldg(m + c + 0)) * (__ldg(g + c + 0) * rsqrtf(__ldg(v + c + 0) + BN_EPS)) + __ldg(b + c + 0);
    o.y = (xv.y - __ldg(m + c + 1)) * (__ldg(g + c + 1) * rsqrtf(__ldg(v + c + 1) + BN_EPS)) + __ldg(b + c + 1);
    o.z = (xv.z - __ldg(m + c + 2)) * (__ldg(g + c + 2) * rsqrtf(__ldg(v + c + 2) + BN_EPS)) + __ldg(b + c + 2);
    o.w = (xv.w - __ldg(m + c + 3)) * (__ldg(g + c + 3) * rsqrtf(__ldg(v + c + 3) + BN_EPS)) + __ldg(b + c + 3);
    ((float4*)g_h0)[idx] = o;
    ((float4*)g_agg1)[idx] = o;
}

// ---------------------------------------------------------------------------
// K2: edge scatter-add, F=128. One warp per edge; lane does one v4 reduction.
// ---------------------------------------------------------------------------
__global__ void scatter128_kernel(const int* __restrict__ src,
                                  const int* __restrict__ dst) {
    int t = blockIdx.x * blockDim.x + threadIdx.x;
    int e = t >> 5;
    if (e >= N_EDGES) return;
    int lane = t & 31;
    int s = clamp_idx(__ldg(src + e));
    int d = clamp_idx(__ldg(dst + e));
    float4 hv = ((const float4*)(g_h0 + (size_t)s * F_IN))[lane];
    float* dp = g_agg1 + (size_t)d * F_IN + lane * 4;
    red_add_v4(dp, hv);
}

// ---------------------------------------------------------------------------
// K3: GEMM1 [50000,128]x[128,256] + bias + BN1 + ReLU -> g_h1.
//     64x64 tile, 256 threads, 4x4 per thread.
// ---------------------------------------------------------------------------
__global__ void gemm1_kernel(const float* __restrict__ W1, const float* __restrict__ b1,
                             const float* __restrict__ bg, const float* __restrict__ bb,
                             const float* __restrict__ bm, const float* __restrict__ bv) {
    __shared__ __align__(16) float sA[64][68];
    __shared__ __align__(16) float sB[64][68];
    const float* A = g_agg1;
    int tid = threadIdx.x;
    int block_m = blockIdx.x * 64;
    int block_n = blockIdx.y * 64;
    int tx = tid & 15, ty = tid >> 4;

    float acc[4][4];
#pragma unroll
    for (int i = 0; i < 4; i++)
#pragma unroll
        for (int j = 0; j < 4; j++) acc[i][j] = 0.f;

    for (int kk = 0; kk < F_IN; kk += 64) {
#pragma unroll
        for (int i = 0; i < 4; i++) {
            int f4 = tid + i * 256;
            int row = f4 >> 4;
            int c4 = f4 & 15;
            int gr = block_m + row;
            float4 val = make_float4(0.f, 0.f, 0.f, 0.f);
            if (gr < N_NODES)
                val = ((const float4*)(A + (size_t)gr * F_IN + kk))[c4];
            *(float4*)&sA[row][c4 * 4] = val;
        }
#pragma unroll
        for (int i = 0; i < 4; i++) {
            int f4 = tid + i * 256;
            int k = f4 >> 4;
            int c4 = f4 & 15;
            float4 val = ((const float4*)(W1 + (size_t)(kk + k) * HID + block_n))[c4];
            *(float4*)&sB[k][c4 * 4] = val;
        }
        __syncthreads();

#pragma unroll
        for (int k = 0; k < 64; k++) {
            float a[4], bvreg[4];
#pragma unroll
            for (int i = 0; i < 4; i++) a[i] = sA[ty * 4 + i][k];
#pragma unroll
            for (int j = 0; j < 4; j++) bvreg[j] = sB[k][tx * 4 + j];
#pragma unroll
            for (int i = 0; i < 4; i++)
#pragma unroll
                for (int j = 0; j < 4; j++) acc[i][j] += a[i] * bvreg[j];
        }
        __syncthreads();
    }

#pragma unroll
    for (int j = 0; j < 4; j++) {
        int c = block_n + tx * 4 + j;
        float s = __ldg(bg + c) * rsqrtf(__ldg(bv + c) + BN_EPS);
        float mu = __ldg(bm + c);
        float be = __ldg(bb + c);
        float bias = __ldg(b1 + c);
#pragma unroll
        for (int i = 0; i < 4; i++) {
            int gr = block_m + ty * 4 + i;
            if (gr < N_NODES) {
                float val = acc[i][j] + bias;
                val = (val - mu) * s + be;
                val = fmaxf(val, 0.f);
                g_h1[(size_t)gr * HID + c] = val;
            }
        }
    }
}

// ---------------------------------------------------------------------------
// K4: GEMM2 [50000,256]x[256,40]. Writes z = h1@W2 to g_z,
//     and z + b2 (self term + bias) to out. One thread per row.
// ---------------------------------------------------------------------------
__global__ void gemm2_kernel(const float* __restrict__ W2, const float* __restrict__ b2,
                             float* __restrict__ out) {
    __shared__ float sW[HID * NCLS];  // 40KB
    int tid = threadIdx.x;
    for (int i = tid; i < HID * NCLS; i += blockDim.x) sW[i] = W2[i];
    __syncthreads();

    int row = blockIdx.x * blockDim.x + tid;
    if (row >= N_NODES) return;

    float acc[NCLS];
#pragma unroll
    for (int c = 0; c < NCLS; c++) acc[c] = 0.f;

    const float4* ap = (const float4*)(g_h1 + (size_t)row * HID);
#pragma unroll 4
    for (int k4 = 0; k4 < HID / 4; k4++) {
        float4 a = ap[k4];
        const float* w0 = &sW[(k4 * 4 + 0) * NCLS];
        const float* w1 = &sW[(k4 * 4 + 1) * NCLS];
        const float* w2 = &sW[(k4 * 4 + 2) * NCLS];
        const float* w3 = &sW[(k4 * 4 + 3) * NCLS];
#pragma unroll
        for (int c = 0; c < NCLS; c++) {
            acc[c] += a.x * w0[c];
            acc[c] += a.y * w1[c];
            acc[c] += a.z * w2[c];
            acc[c] += a.w * w3[c];
        }
    }

    float* zp = g_z + (size_t)row * NCLS;
    float* op = out + (size_t)row * NCLS;
#pragma unroll
    for (int c = 0; c < NCLS; c++) {
        zp[c] = acc[c];
        op[c] = acc[c] + __ldg(b2 + c);
    }
}

// ---------------------------------------------------------------------------
// K5: edge scatter-add in logit space (40 floats/edge = 10 float4 chunks).
//     out[dst] += z[src]. Thread = (edge, chunk).
// ---------------------------------------------------------------------------
__global__ void scatter40_kernel(const int* __restrict__ src,
                                 const int* __restrict__ dst,
                                 float* __restrict__ out) {
    int t = blockIdx.x * blockDim.x + threadIdx.x;
    int e = t / (NCLS / 4);
    if (e >= N_EDGES) return;
    int chunk = t - e * (NCLS / 4);
    int s = clamp_idx(__ldg(src + e));
    int d = clamp_idx(__ldg(dst + e));
    float4 v = *(const float4*)(g_z + (size_t)s * NCLS + chunk * 4);
    float* p = out + (size_t)d * NCLS + chunk * 4;
    red_add_v4(p, v);
}

// ---------------------------------------------------------------------------
extern "C" void kernel_launch(void* const* d_in, const int* in_sizes, int n_in,
                              void* d_out, int out_size) {
    const float* x = (const float*)d_in[0];
    const int* ei = (const int*)d_in[1];   // int32 (jax x64-disabled)
    const float* bn0g = (const float*)d_in[2];
    const float* bn0b = (const float*)d_in[3];
    const float* bn0m = (const float*)d_in[4];
    const float* bn0v = (const float*)d_in[5];
    const float* W1 = (const float*)d_in[6];
    const float* b1 = (const float*)d_in[7];
    const float* bn1g = (const float*)d_in[8];
    const float* bn1b = (const float*)d_in[9];
    const float* bn1m = (const float*)d_in[10];
    const float* bn1v = (const float*)d_in[11];
    const float* W2 = (const float*)d_in[12];
    const float* b2 = (const float*)d_in[13];
    float* out = (float*)d_out;

    const int* src = ei;
    const int* dst = ei + N_EDGES;

    // K1: BN0 -> g_h0, g_agg1
    {
        int total = N_NODES * (F_IN / 4);
        bn0_kernel<<<(total + 255) / 256, 256>>>((const float4*)x, bn0g, bn0b, bn0m, bn0v);
    }
    // K2: 128-dim scatter-add into g_agg1 (v4 reductions)
    {
        long long threads = (long long)N_EDGES * 32;
        scatter128_kernel<<<(int)((threads + 255) / 256), 256>>>(src, dst);
    }
    // K3: GEMM1 + BN1 + ReLU -> g_h1
    {
        dim3 grid((N_NODES + 63) / 64, HID / 64);
        gemm1_kernel<<<grid, 256>>>(W1, b1, bn1g, bn1b, bn1m, bn1v);
    }
    // K4: GEMM2 -> g_z, out = z + b2
    {
        gemm2_kernel<<<(N_NODES + 255) / 256, 256>>>(W2, b2, out);
    }
    // K5: 40-dim scatter-add into out (associativity: (h+Ah)W = hW + A(hW))
    {
        long long threads = (long long)N_EDGES * (NCLS / 4);
        scatter40_kernel<<<(int)((threads + 255) / 256), 256>>>(src, dst, out);
    }
}

// round 7
// speedup vs baseline: 2.8390x; 1.1514x over previous
#include <cuda_runtime.h>
#include <math.h>

#define N_NODES 50000
#define F_IN 128
#define HID 256
#define NCLS 40
#define N_EDGES 600000
#define BN_EPS 1e-5f

// Scratch (static device globals -- no runtime allocation allowed)
__device__ float g_h0[N_NODES * F_IN];    // BN0(x)
__device__ float g_agg1[N_NODES * F_IN];  // h0 + scatter
__device__ float g_h1[N_NODES * HID];     // relu(BN1(agg1 @ W1 + b1))
__device__ float g_z[N_NODES * NCLS];     // h1 @ W2 (pre-aggregation logits)

__device__ __forceinline__ int clamp_idx(int i) {
    i = i < 0 ? 0 : i;
    return i >= N_NODES ? N_NODES - 1 : i;
}

__device__ __forceinline__ void red_add_v4(float* p, float4 v) {
    asm volatile("red.global.add.v4.f32 [%0], {%1, %2, %3, %4};"
                 :: "l"(p), "f"(v.x), "f"(v.y), "f"(v.z), "f"(v.w)
                 : "memory");
}

// ---------------------------------------------------------------------------
// K1: BN0 over input features; writes g_h0 and initializes g_agg1 (self term)
// ---------------------------------------------------------------------------
__global__ void bn0_kernel(const float4* __restrict__ x,
                           const float* __restrict__ g, const float* __restrict__ b,
                           const float* __restrict__ m, const float* __restrict__ v) {
    int idx = blockIdx.x * blockDim.x + threadIdx.x;
    const int total = N_NODES * (F_IN / 4);
    if (idx >= total) return;
    int c = (idx & (F_IN / 4 - 1)) * 4;
    float4 xv = x[idx];
    float4 o;
    o.x = (xv.x - __ldg(m + c + 0)) * (__ldg(g + c + 0) * rsqrtf(__ldg(v + c + 0) + BN_EPS)) + __ldg(b + c + 0);
    o.y = (xv.y - __ldg(m + c + 1)) * (__ldg(g + c + 1) * rsqrtf(__ldg(v + c + 1) + BN_EPS)) + __ldg(b + c + 1);
    o.z = (xv.z - __ldg(m + c + 2)) * (__ldg(g + c + 2) * rsqrtf(__ldg(v + c + 2) + BN_EPS)) + __ldg(b + c + 2);
    o.w = (xv.w - __ldg(m + c + 3)) * (__ldg(g + c + 3) * rsqrtf(__ldg(v + c + 3) + BN_EPS)) + __ldg(b + c + 3);
    ((float4*)g_h0)[idx] = o;
    ((float4*)g_agg1)[idx] = o;
}

// ---------------------------------------------------------------------------
// K2: edge scatter-add, F=128. One warp per edge; lane does one v4 reduction.
// ---------------------------------------------------------------------------
__global__ void scatter128_kernel(const int* __restrict__ src,
                                  const int* __restrict__ dst) {
    int t = blockIdx.x * blockDim.x + threadIdx.x;
    int e = t >> 5;
    if (e >= N_EDGES) return;
    int lane = t & 31;
    int s = clamp_idx(__ldg(src + e));
    int d = clamp_idx(__ldg(dst + e));
    float4 hv = ((const float4*)(g_h0 + (size_t)s * F_IN))[lane];
    float* dp = g_agg1 + (size_t)d * F_IN + lane * 4;
    red_add_v4(dp, hv);
}

// ---------------------------------------------------------------------------
// K3: GEMM1 [50000,128]x[128,256] + bias + BN1 + ReLU -> g_h1.
//     64x64 tile, 256 threads, 4x4 per thread.
// ---------------------------------------------------------------------------
__global__ void gemm1_kernel(const float* __restrict__ W1, const float* __restrict__ b1,
                             const float* __restrict__ bg, const float* __restrict__ bb,
                             const float* __restrict__ bm, const float* __restrict__ bv) {
    __shared__ __align__(16) float sA[64][68];
    __shared__ __align__(16) float sB[64][68];
    const float* A = g_agg1;
    int tid = threadIdx.x;
    int block_m = blockIdx.x * 64;
    int block_n = blockIdx.y * 64;
    int tx = tid & 15, ty = tid >> 4;

    float acc[4][4];
#pragma unroll
    for (int i = 0; i < 4; i++)
#pragma unroll
        for (int j = 0; j < 4; j++) acc[i][j] = 0.f;

    for (int kk = 0; kk < F_IN; kk += 64) {
#pragma unroll
        for (int i = 0; i < 4; i++) {
            int f4 = tid + i * 256;
            int row = f4 >> 4;
            int c4 = f4 & 15;
            int gr = block_m + row;
            float4 val = make_float4(0.f, 0.f, 0.f, 0.f);
            if (gr < N_NODES)
                val = ((const float4*)(A + (size_t)gr * F_IN + kk))[c4];
            *(float4*)&sA[row][c4 * 4] = val;
        }
#pragma unroll
        for (int i = 0; i < 4; i++) {
            int f4 = tid + i * 256;
            int k = f4 >> 4;
            int c4 = f4 & 15;
            float4 val = ((const float4*)(W1 + (size_t)(kk + k) * HID + block_n))[c4];
            *(float4*)&sB[k][c4 * 4] = val;
        }
        __syncthreads();

#pragma unroll
        for (int k = 0; k < 64; k++) {
            float a[4], bvreg[4];
#pragma unroll
            for (int i = 0; i < 4; i++) a[i] = sA[ty * 4 + i][k];
#pragma unroll
            for (int j = 0; j < 4; j++) bvreg[j] = sB[k][tx * 4 + j];
#pragma unroll
            for (int i = 0; i < 4; i++)
#pragma unroll
                for (int j = 0; j < 4; j++) acc[i][j] += a[i] * bvreg[j];
        }
        __syncthreads();
    }

#pragma unroll
    for (int j = 0; j < 4; j++) {
        int c = block_n + tx * 4 + j;
        float s = __ldg(bg + c) * rsqrtf(__ldg(bv + c) + BN_EPS);
        float mu = __ldg(bm + c);
        float be = __ldg(bb + c);
        float bias = __ldg(b1 + c);
#pragma unroll
        for (int i = 0; i < 4; i++) {
            int gr = block_m + ty * 4 + i;
            if (gr < N_NODES) {
                float val = acc[i][j] + bias;
                val = (val - mu) * s + be;
                val = fmaxf(val, 0.f);
                g_h1[(size_t)gr * HID + c] = val;
            }
        }
    }
}

// ---------------------------------------------------------------------------
// K4: GEMM2 [50000,256]x[256,40] tiled. BM=128, BN=40 (full), BK=32.
//     256 threads, each computes 4 rows x 5 cols. Writes z to g_z and
//     z + b2 (self term) to out.
// ---------------------------------------------------------------------------
__global__ void gemm2_kernel(const float* __restrict__ W2, const float* __restrict__ b2,
                             float* __restrict__ out) {
    __shared__ float sA[128][33];        // [row][k], odd stride -> conflict-free
    __shared__ float sB[32][41];         // [k][col]
    int tid = threadIdx.x;
    int tx = tid & 7;                    // 0..7  -> 5 cols each
    int ty = tid >> 3;                   // 0..31 -> 4 rows each
    int block_m = blockIdx.x * 128;

    float acc[4][5];
#pragma unroll
    for (int i = 0; i < 4; i++)
#pragma unroll
        for (int j = 0; j < 5; j++) acc[i][j] = 0.f;

    for (int kk = 0; kk < HID; kk += 32) {
        // Load A tile: 128 rows x 32 k = 1024 float4; 4 per thread
#pragma unroll
        for (int i = 0; i < 4; i++) {
            int f4 = tid + i * 256;      // 0..1023
            int row = f4 >> 3;           // 0..127
            int c4 = f4 & 7;             // 0..7
            int gr = block_m + row;
            float4 v = make_float4(0.f, 0.f, 0.f, 0.f);
            if (gr < N_NODES)
                v = ((const float4*)(g_h1 + (size_t)gr * HID + kk))[c4];
            sA[row][c4 * 4 + 0] = v.x;
            sA[row][c4 * 4 + 1] = v.y;
            sA[row][c4 * 4 + 2] = v.z;
            sA[row][c4 * 4 + 3] = v.w;
        }
        // Load B tile: W2 rows kk..kk+31, all 40 cols = 1280 floats; 5 per thread
#pragma unroll
        for (int i = 0; i < 5; i++) {
            int idx = tid + i * 256;     // 0..1279
            int k = idx / NCLS;
            int c = idx - k * NCLS;
            sB[k][c] = W2[(size_t)(kk + k) * NCLS + c];
        }
        __syncthreads();

#pragma unroll
        for (int k = 0; k < 32; k++) {
            float a[4], bv[5];
#pragma unroll
            for (int i = 0; i < 4; i++) a[i] = sA[ty * 4 + i][k];
#pragma unroll
            for (int j = 0; j < 5; j++) bv[j] = sB[k][tx * 5 + j];
#pragma unroll
            for (int i = 0; i < 4; i++)
#pragma unroll
                for (int j = 0; j < 5; j++) acc[i][j] += a[i] * bv[j];
        }
        __syncthreads();
    }

    // Epilogue: z -> g_z; z + b2 -> out
    float bias[5];
#pragma unroll
    for (int j = 0; j < 5; j++) bias[j] = __ldg(b2 + tx * 5 + j);
#pragma unroll
    for (int i = 0; i < 4; i++) {
        int gr = block_m + ty * 4 + i;
        if (gr < N_NODES) {
            float* zp = g_z + (size_t)gr * NCLS + tx * 5;
            float* op = out + (size_t)gr * NCLS + tx * 5;
#pragma unroll
            for (int j = 0; j < 5; j++) {
                zp[j] = acc[i][j];
                op[j] = acc[i][j] + bias[j];
            }
        }
    }
}

// ---------------------------------------------------------------------------
// K5: edge scatter-add in logit space (40 floats/edge = 10 float4 chunks).
//     out[dst] += z[src]. Thread = (edge, chunk).
// ---------------------------------------------------------------------------
__global__ void scatter40_kernel(const int* __restrict__ src,
                                 const int* __restrict__ dst,
                                 float* __restrict__ out) {
    int t = blockIdx.x * blockDim.x + threadIdx.x;
    int e = t / (NCLS / 4);
    if (e >= N_EDGES) return;
    int chunk = t - e * (NCLS / 4);
    int s = clamp_idx(__ldg(src + e));
    int d = clamp_idx(__ldg(dst + e));
    float4 v = *(const float4*)(g_z + (size_t)s * NCLS + chunk * 4);
    float* p = out + (size_t)d * NCLS + chunk * 4;
    red_add_v4(p, v);
}

// ---------------------------------------------------------------------------
extern "C" void kernel_launch(void* const* d_in, const int* in_sizes, int n_in,
                              void* d_out, int out_size) {
    const float* x = (const float*)d_in[0];
    const int* ei = (const int*)d_in[1];   // int32 (jax x64-disabled)
    const float* bn0g = (const float*)d_in[2];
    const float* bn0b = (const float*)d_in[3];
    const float* bn0m = (const float*)d_in[4];
    const float* bn0v = (const float*)d_in[5];
    const float* W1 = (const float*)d_in[6];
    const float* b1 = (const float*)d_in[7];
    const float* bn1g = (const float*)d_in[8];
    const float* bn1b = (const float*)d_in[9];
    const float* bn1m = (const float*)d_in[10];
    const float* bn1v = (const float*)d_in[11];
    const float* W2 = (const float*)d_in[12];
    const float* b2 = (const float*)d_in[13];
    float* out = (float*)d_out;

    const int* src = ei;
    const int* dst = ei + N_EDGES;

    // K1: BN0 -> g_h0, g_agg1
    {
        int total = N_NODES * (F_IN / 4);
        bn0_kernel<<<(total + 255) / 256, 256>>>((const float4*)x, bn0g, bn0b, bn0m, bn0v);
    }
    // K2: 128-dim scatter-add into g_agg1 (v4 reductions)
    {
        long long threads = (long long)N_EDGES * 32;
        scatter128_kernel<<<(int)((threads + 255) / 256), 256>>>(src, dst);
    }
    // K3: GEMM1 + BN1 + ReLU -> g_h1
    {
        dim3 grid((N_NODES + 63) / 64, HID / 64);
        gemm1_kernel<<<grid, 256>>>(W1, b1, bn1g, bn1b, bn1m, bn1v);
    }
    // K4: GEMM2 (tiled) -> g_z, out = z + b2
    {
        gemm2_kernel<<<(N_NODES + 127) / 128, 256>>>(W2, b2, out);
    }
    // K5: 40-dim scatter-add into out (associativity: (h+Ah)W = hW + A(hW))
    {
        long long threads = (long long)N_EDGES * (NCLS / 4);
        scatter40_kernel<<<(int)((threads + 255) / 256), 256>>>(src, dst, out);
    }
}